// round 3
// baseline (speedup 1.0000x reference)
#include <cuda_runtime.h>

// NeuralClickModel: 4096 independent GRU chains (D=256, SLATE=20 steps).
// Persistent-CTA design: 128 CTAs x 32 sequences, 256 threads each.
// Per step per CTA: three K=256 GEMM passes over a [32 x 128]-per-chunk C tile:
//   acc1 += e @ W_ih[:, 0:256]^T      (P part; also accumulates GH for r/z chunks)
//   accQ += e @ W_ih[:, 256:512]^T    (Q part, scaled by per-row m at writeout)
//   GH   += h @ W_hh^T                (into acc1 for r/z; separate for n-gate)
// Gates computed elementwise from SMEM, y-dot reduced per sequence, m=sigmoid(y).

#define NSEQ   32
#define THREADS 256
#define DD     256
#define SLATE_ 20
#define EP     260   // pitch for h/e rows (mult of 4 for float4)
#define SP     777   // pitch for S rows (odd vs 32 banks -> conflict-free column reads)
#define HP     261   // pitch for HN rows
#define BP     132   // pitch for Bs staging rows

__device__ __forceinline__ float sigmoidf_(float x) {
    return 1.0f / (1.0f + __expf(-x));
}

// One full K=256 pass: C[32 x 128chunk] += A[32 x 256] * W^T, W rows = chunk's 128 g-rows.
// A in SMEM (pitch EP), W streamed global->SMEM (Bs) in 32-wide k blocks.
__device__ __forceinline__ void gemm_k256(
    const float* __restrict__ gW, int ldw,
    const float* __restrict__ sA,
    float* __restrict__ Bs,
    float* __restrict__ acc,
    int tg, int tn, int tid)
{
#pragma unroll 1
    for (int kb = 0; kb < 256; kb += 32) {
        __syncthreads();   // protect Bs from previous block's readers
        // stage 128 g x 32 k (transposed into Bs[k][g]); 4 float4 per thread, coalesced
#pragma unroll
        for (int i = 0; i < 4; i++) {
            int lin = i * 256 + tid;       // 0..1023
            int gr  = lin >> 3;            // 0..127
            int k4  = (lin & 7) << 2;      // 0,4,...,28
            float4 v = *(const float4*)(gW + gr * ldw + kb + k4);
            Bs[(k4 + 0) * BP + gr] = v.x;
            Bs[(k4 + 1) * BP + gr] = v.y;
            Bs[(k4 + 2) * BP + gr] = v.z;
            Bs[(k4 + 3) * BP + gr] = v.w;
        }
        __syncthreads();
        const float* aRow = sA + (tn * 4) * EP + kb;
#pragma unroll
        for (int k = 0; k < 32; k += 4) {
            float4 b0 = *(const float4*)(Bs + (k + 0) * BP + tg * 4);
            float4 b1 = *(const float4*)(Bs + (k + 1) * BP + tg * 4);
            float4 b2 = *(const float4*)(Bs + (k + 2) * BP + tg * 4);
            float4 b3 = *(const float4*)(Bs + (k + 3) * BP + tg * 4);
#pragma unroll
            for (int j = 0; j < 4; j++) {
                float4 a = *(const float4*)(aRow + j * EP + k);
                float* ac = acc + j * 4;
                ac[0] = fmaf(a.x, b0.x, ac[0]);
                ac[1] = fmaf(a.x, b0.y, ac[1]);
                ac[2] = fmaf(a.x, b0.z, ac[2]);
                ac[3] = fmaf(a.x, b0.w, ac[3]);
                ac[0] = fmaf(a.y, b1.x, ac[0]);
                ac[1] = fmaf(a.y, b1.y, ac[1]);
                ac[2] = fmaf(a.y, b1.z, ac[2]);
                ac[3] = fmaf(a.y, b1.w, ac[3]);
                ac[0] = fmaf(a.z, b2.x, ac[0]);
                ac[1] = fmaf(a.z, b2.y, ac[1]);
                ac[2] = fmaf(a.z, b2.z, ac[2]);
                ac[3] = fmaf(a.z, b2.w, ac[3]);
                ac[0] = fmaf(a.w, b3.x, ac[0]);
                ac[1] = fmaf(a.w, b3.y, ac[1]);
                ac[2] = fmaf(a.w, b3.z, ac[2]);
                ac[3] = fmaf(a.w, b3.w, ac[3]);
            }
        }
    }
}

__global__ void __launch_bounds__(THREADS, 1)
ncm_kernel(const int* __restrict__ item_idxs,
           const int* __restrict__ user_idxs,
           const float* __restrict__ item_table,
           const float* __restrict__ user_table,
           const float* __restrict__ W_ih,
           const float* __restrict__ W_hh,
           const float* __restrict__ b_ih,
           const float* __restrict__ b_hh,
           const float* __restrict__ W_out,
           const float* __restrict__ b_out,
           float* __restrict__ out)
{
    extern __shared__ float smf[];
    float* h_s  = smf;                   // 32*EP
    float* e_s  = h_s  + NSEQ * EP;      // 32*EP
    float* S_s  = e_s  + NSEQ * EP;      // 32*SP  (gi+gh for r,z; gi for n)
    float* HN_s = S_s  + NSEQ * SP;      // 32*HP  (gh n-part)
    float* Bs   = HN_s + NSEQ * HP;      // 32*BP
    float* m_s  = Bs   + 32 * BP;        // 32
    float* yp_s = m_s  + 32;             // 256 partials
    float* wo_s = yp_s + THREADS;        // 256 W_out

    const int tid = threadIdx.x;
    const int tg = tid & 31;
    const int tn = tid >> 5;
    const int n0 = blockIdx.x * NSEQ;

    wo_s[tid] = W_out[tid];

    // h0 = user embedding, m0 = 1
    {
        int r  = tid >> 3;
        int c0 = (tid & 7) << 2;
        int uidx = user_idxs[n0 + r];
        const float* src = user_table + (size_t)uidx * DD;
#pragma unroll
        for (int i = 0; i < 8; i++) {
            int c = c0 + i * 32;
            *(float4*)(h_s + r * EP + c) = *(const float4*)(src + c);
        }
    }
    if (tid < NSEQ) m_s[tid] = 1.0f;
    const float bo = b_out[0];

#pragma unroll 1
    for (int s = 0; s < SLATE_; s++) {
        __syncthreads();   // prev step's h/m/out complete; e no longer read
        // gather item embeddings for this slate step
        {
            int r  = tid >> 3;
            int c0 = (tid & 7) << 2;
            int iidx = item_idxs[(n0 + r) * SLATE_ + s];
            const float* src = item_table + (size_t)iidx * DD;
#pragma unroll
            for (int i = 0; i < 8; i++) {
                int c = c0 + i * 32;
                *(float4*)(e_s + r * EP + c) = *(const float4*)(src + c);
            }
        }
        // e-stores are made visible by the __syncthreads() at the top of gemm_k256

#pragma unroll 1
        for (int chunk = 0; chunk < 6; chunk++) {
            float acc1[16], accQ[16];
#pragma unroll
            for (int i = 0; i < 16; i++) { acc1[i] = 0.0f; accQ[i] = 0.0f; }
            const float* Wi = W_ih + (size_t)chunk * 128 * 512;
            gemm_k256(Wi,       512, e_s, Bs, acc1, tg, tn, tid);   // P
            gemm_k256(Wi + 256, 512, e_s, Bs, accQ, tg, tn, tid);   // Q

            int g0 = chunk * 128 + tg * 4;
            float4 bi4 = *(const float4*)(b_ih + g0);
            float4 bh4 = *(const float4*)(b_hh + g0);
            float mreg[4];
#pragma unroll
            for (int j = 0; j < 4; j++) mreg[j] = m_s[tn * 4 + j];

            const float* Wh = W_hh + (size_t)chunk * 128 * 256;
            if (chunk < 4) {
                // r/z range: GH accumulates straight into acc1 (gi+gh combined)
                gemm_k256(Wh, 256, h_s, Bs, acc1, tg, tn, tid);
#pragma unroll
                for (int j = 0; j < 4; j++) {
                    float* Sr = S_s + (tn * 4 + j) * SP + g0;
                    Sr[0] = acc1[j*4+0] + mreg[j] * accQ[j*4+0] + bi4.x + bh4.x;
                    Sr[1] = acc1[j*4+1] + mreg[j] * accQ[j*4+1] + bi4.y + bh4.y;
                    Sr[2] = acc1[j*4+2] + mreg[j] * accQ[j*4+2] + bi4.z + bh4.z;
                    Sr[3] = acc1[j*4+3] + mreg[j] * accQ[j*4+3] + bi4.w + bh4.w;
                }
            } else {
                // n-gate range: keep gi (S) and gh (HN) separate
                float accG[16];
#pragma unroll
                for (int i = 0; i < 16; i++) accG[i] = 0.0f;
                gemm_k256(Wh, 256, h_s, Bs, accG, tg, tn, tid);
                int d0 = g0 - 512;
#pragma unroll
                for (int j = 0; j < 4; j++) {
                    float* Sr = S_s  + (tn * 4 + j) * SP + g0;
                    float* Hr = HN_s + (tn * 4 + j) * HP + d0;
                    Sr[0] = acc1[j*4+0] + mreg[j] * accQ[j*4+0] + bi4.x;
                    Sr[1] = acc1[j*4+1] + mreg[j] * accQ[j*4+1] + bi4.y;
                    Sr[2] = acc1[j*4+2] + mreg[j] * accQ[j*4+2] + bi4.z;
                    Sr[3] = acc1[j*4+3] + mreg[j] * accQ[j*4+3] + bi4.w;
                    Hr[0] = accG[j*4+0] + bh4.x;
                    Hr[1] = accG[j*4+1] + bh4.y;
                    Hr[2] = accG[j*4+2] + bh4.z;
                    Hr[3] = accG[j*4+3] + bh4.w;
                }
            }
        }
        __syncthreads();   // S, HN complete

        // Gate math + h update + y partial dot. Lane = sequence (conflict-free
        // column reads thanks to odd pitches SP/HP).
        {
            int n  = tid & 31;
            int ds = tid >> 5;
            float ypart = 0.0f;
            const float* Sn = S_s  + n * SP;
            const float* Hn = HN_s + n * HP;
            float* hn = h_s + n * EP;
#pragma unroll 4
            for (int i = 0; i < 32; i++) {
                int d = ds + (i << 3);
                float r  = sigmoidf_(Sn[d]);
                float z  = sigmoidf_(Sn[256 + d]);
                float nv = tanhf(fmaf(r, Hn[d], Sn[512 + d]));
                float ho = hn[d];
                float hv = fmaf(z, ho - nv, nv);   // (1-z)*nv + z*ho
                hn[d] = hv;
                ypart = fmaf(hv, wo_s[d], ypart);
            }
            yp_s[tid] = ypart;
        }
        __syncthreads();
        if (tid < NSEQ) {
            float y = bo;
#pragma unroll
            for (int j = 0; j < 8; j++) y += yp_s[j * 32 + tid];
            out[(n0 + tid) * SLATE_ + s] = y;      // pre-sigmoid logit
            m_s[tid] = sigmoidf_(y);
        }
    }
}

extern "C" void kernel_launch(void* const* d_in, const int* in_sizes, int n_in,
                              void* d_out, int out_size) {
    const int*   item_idxs  = (const int*)d_in[0];
    const int*   user_idxs  = (const int*)d_in[1];
    /* d_in[2] = responses (unused by reference math) */
    const float* item_table = (const float*)d_in[3];
    const float* user_table = (const float*)d_in[4];
    const float* W_ih       = (const float*)d_in[5];
    const float* W_hh       = (const float*)d_in[6];
    const float* b_ih       = (const float*)d_in[7];
    const float* b_hh       = (const float*)d_in[8];
    const float* W_out      = (const float*)d_in[9];
    const float* b_out      = (const float*)d_in[10];
    float* out = (float*)d_out;

    const int smem_bytes = (NSEQ * EP * 2 + NSEQ * SP + NSEQ * HP +
                            32 * BP + 32 + THREADS + 256) * (int)sizeof(float);
    cudaFuncSetAttribute(ncm_kernel, cudaFuncAttributeMaxDynamicSharedMemorySize,
                         smem_bytes);
    ncm_kernel<<<128, THREADS, smem_bytes>>>(
        item_idxs, user_idxs, item_table, user_table,
        W_ih, W_hh, b_ih, b_hh, W_out, b_out, out);
}

// round 7
// speedup vs baseline: 3.3424x; 3.3424x over previous
#include <cuda_runtime.h>
#include <cuda_bf16.h>
#include <cstdint>

// NeuralClickModel via mma.sync (legacy HMMA, no 'a'-gated instructions).
// Per step: G[4096 x 1024] = A[4096 x 768] @ Wbig^T with split-bf16 3-MMA
// (Ahi*Bhi + Ahi*Blo + Alo*Bhi ~ fp32 accuracy), then elementwise GRU kernel.
//
// A columns: [0:256)=e, [256:512)=m*e, [512:768)=h
// G columns: [0:256)=r-sum(gi+gh), [256:512)=z-sum, [512:768)=gi_n, [768:1024)=gh_n
// Wbig rows: n<512: [W_ih | W_hh]; 512<=n<768: [W_ih_n | 0]; 768<=n<1024: [0 | W_hh_n]

#define NSEQT 4096
#define DD    256
#define SLATE_ 20
#define KTOT  768
#define GTOT  1024
#define KC    64     // k-chunk (64 bf16 = 128B rows -> SW128 swizzle)
#define NKC   12     // KTOT / KC
#define MT    128
#define NT    256
#define NMT   32     // 4096/128
#define NNT   4      // 1024/256

#define ABYTES (MT * KC * 2)               // 16384 per A sub-tile
#define BBYTES (NT * KC * 2)               // 32768 per B sub-tile
#define BUFB   (2 * ABYTES + 2 * BBYTES)   // 98304 per pipeline buffer
#define SMTOT  (2 * BUFB)                  // 196608 total dynamic smem

// -------- device scratch (static; no allocation) --------
__device__ __align__(16) __nv_bfloat16 g_A_hi[NSEQT * KTOT];
__device__ __align__(16) __nv_bfloat16 g_A_lo[NSEQT * KTOT];
__device__ __align__(16) __nv_bfloat16 g_B_hi[GTOT * KTOT];
__device__ __align__(16) __nv_bfloat16 g_B_lo[GTOT * KTOT];
__device__ float g_G[NSEQT * GTOT];
__device__ float g_h[NSEQT * DD];

// -------- helpers --------
__device__ __forceinline__ uint32_t smem_u32(const void* p) {
    uint32_t a;
    asm("{ .reg .u64 t; cvta.to.shared.u64 t, %1; cvt.u32.u64 %0, t; }" : "=r"(a) : "l"(p));
    return a;
}
__device__ __forceinline__ int swz(int byt) { return byt ^ ((byt >> 3) & 0x70); }

__device__ __forceinline__ void cp16(uint32_t s, const void* g) {
    asm volatile("cp.async.cg.shared.global [%0], [%1], 16;" :: "r"(s), "l"(g) : "memory");
}
__device__ __forceinline__ void cp_commit() {
    asm volatile("cp.async.commit_group;" ::: "memory");
}
template <int N> __device__ __forceinline__ void cp_wait() {
    asm volatile("cp.async.wait_group %0;" :: "n"(N) : "memory");
}
__device__ __forceinline__ void ldm4(uint32_t addr, uint32_t* r) {
    asm volatile("ldmatrix.sync.aligned.m8n8.x4.shared.b16 {%0,%1,%2,%3}, [%4];"
                 : "=r"(r[0]), "=r"(r[1]), "=r"(r[2]), "=r"(r[3]) : "r"(addr));
}
__device__ __forceinline__ void mma_bf16(float* d, const uint32_t* a, const uint32_t* b) {
    asm volatile(
        "mma.sync.aligned.m16n8k16.row.col.f32.bf16.bf16.f32 "
        "{%0,%1,%2,%3}, {%4,%5,%6,%7}, {%8,%9}, {%0,%1,%2,%3};"
        : "+f"(d[0]), "+f"(d[1]), "+f"(d[2]), "+f"(d[3])
        : "r"(a[0]), "r"(a[1]), "r"(a[2]), "r"(a[3]), "r"(b[0]), "r"(b[1]));
}

// blocked + swizzled gmem layouts (element index)
__device__ __forceinline__ int a_addr(int n, int k) {
    int blk = (n >> 7) * NKC + (k >> 6);
    int byt = (n & 127) * 128 + (k & 63) * 2;
    byt = swz(byt);
    return blk * (MT * KC) + (byt >> 1);
}
__device__ __forceinline__ int b_addr(int n, int k) {
    int blk = (n >> 8) * NKC + (k >> 6);
    int byt = (n & 255) * 128 + (k & 63) * 2;
    byt = swz(byt);
    return blk * (NT * KC) + (byt >> 1);
}
__device__ __forceinline__ void split2(float v, __nv_bfloat16& hi, __nv_bfloat16& lo) {
    hi = __float2bfloat16(v);
    lo = __float2bfloat16(v - __bfloat162float(hi));
}
__device__ __forceinline__ float sigmoidf_(float x) { return 1.0f / (1.0f + __expf(-x)); }

// -------- weight split + pre-swizzle (once per launch) --------
__global__ void wsplit_kernel(const float* __restrict__ W_ih,
                              const float* __restrict__ W_hh) {
    int idx = blockIdx.x * blockDim.x + threadIdx.x;
    if (idx >= GTOT * KTOT) return;
    int n = idx / KTOT, k = idx - n * KTOT;
    float w = 0.0f;
    if (n < 512) {
        w = (k < 512) ? W_ih[n * 512 + k] : W_hh[n * 256 + (k - 512)];
    } else if (n < 768) {
        if (k < 512) w = W_ih[n * 512 + k];
    } else {
        if (k >= 512) w = W_hh[(n - 256) * 256 + (k - 512)];
    }
    __nv_bfloat16 hi, lo;
    split2(w, hi, lo);
    int a = b_addr(n, k);
    g_B_hi[a] = hi;
    g_B_lo[a] = lo;
}

// -------- step-0 prep: h0, m0=1, A for step 0 --------
__global__ void prep0_kernel(const int* __restrict__ item_idxs,
                             const int* __restrict__ user_idxs,
                             const float* __restrict__ item_table,
                             const float* __restrict__ user_table) {
    int n = blockIdx.x;
    int d = threadIdx.x;
    float e = item_table[(size_t)item_idxs[n * SLATE_] * DD + d];
    float h0 = user_table[(size_t)user_idxs[n] * DD + d];
    g_h[n * DD + d] = h0;
    __nv_bfloat16 hi, lo;
    split2(e, hi, lo);
    int a0 = a_addr(n, d);       g_A_hi[a0] = hi; g_A_lo[a0] = lo;  // e
    int a1 = a_addr(n, 256 + d); g_A_hi[a1] = hi; g_A_lo[a1] = lo;  // m*e, m=1
    split2(h0, hi, lo);
    int a2 = a_addr(n, 512 + d); g_A_hi[a2] = hi; g_A_lo[a2] = lo;  // h
}

// -------- staging: one k-chunk (pre-swizzled -> pure linear 16B copies) --------
__device__ __forceinline__ void stage_chunk(uint32_t dst,
                                            const char* pAh, const char* pAl,
                                            const char* pBh, const char* pBl,
                                            int tid) {
#pragma unroll
    for (int i = 0; i < 4; i++) {
        int o = (tid + i * 256) * 16;
        cp16(dst + o, pAh + o);
        cp16(dst + ABYTES + o, pAl + o);
    }
#pragma unroll
    for (int i = 0; i < 8; i++) {
        int o = (tid + i * 256) * 16;
        cp16(dst + 2 * ABYTES + o, pBh + o);
        cp16(dst + 2 * ABYTES + BBYTES + o, pBl + o);
    }
}

// -------- GEMM: G = A @ Wbig^T, split-bf16 3-MMA, register accumulators --------
__global__ void __launch_bounds__(256, 1) gemm_step_kernel() {
    extern __shared__ char smem[];
    const uint32_t sb = smem_u32(smem);
    const int tid = threadIdx.x;
    const int lane = tid & 31;
    const int warp = tid >> 5;
    const int wm = warp & 1;    // 2 M groups of 64
    const int wn = warp >> 1;   // 4 N groups of 64
    const int mt = blockIdx.x & (NMT - 1);
    const int nt = blockIdx.x >> 5;

    const char* gAh = (const char*)g_A_hi + (size_t)mt * NKC * ABYTES;
    const char* gAl = (const char*)g_A_lo + (size_t)mt * NKC * ABYTES;
    const char* gBh = (const char*)g_B_hi + (size_t)nt * NKC * BBYTES;
    const char* gBl = (const char*)g_B_lo + (size_t)nt * NKC * BBYTES;

    float acc[4][8][4];
#pragma unroll
    for (int mi = 0; mi < 4; mi++)
#pragma unroll
        for (int ni = 0; ni < 8; ni++)
#pragma unroll
            for (int q = 0; q < 4; q++) acc[mi][ni][q] = 0.0f;

    // per-lane ldmatrix address pieces
    const int arow  = wm * 64 + (lane & 15);                      // + mi*16
    const int acolb = (lane >> 4) * 16;                           // + kk*32
    const int brow  = wn * 64 + ((lane >> 4) << 3) + (lane & 7);  // + j*16
    const int bcolb = ((lane >> 3) & 1) * 16;                     // + kk*32

    stage_chunk(sb, gAh, gAl, gBh, gBl, tid);
    cp_commit();

#pragma unroll 1
    for (int c = 0; c < NKC; c++) {
        const int buf = c & 1;
        if (c + 1 < NKC) {
            stage_chunk(sb + (buf ^ 1) * BUFB,
                        gAh + (c + 1) * ABYTES, gAl + (c + 1) * ABYTES,
                        gBh + (c + 1) * BBYTES, gBl + (c + 1) * BBYTES, tid);
            cp_commit();
            cp_wait<1>();
        } else {
            cp_wait<0>();
        }
        __syncthreads();

        const uint32_t base = sb + buf * BUFB;
#pragma unroll
        for (int kk = 0; kk < 4; kk++) {
            uint32_t Ah[4][4], Al[4][4];
#pragma unroll
            for (int mi = 0; mi < 4; mi++) {
                uint32_t ad = base + swz((arow + mi * 16) * 128 + kk * 32 + acolb);
                ldm4(ad, Ah[mi]);
                ldm4(ad + ABYTES, Al[mi]);
            }
            uint32_t Bh[4][4], Bl[4][4];
#pragma unroll
            for (int j = 0; j < 4; j++) {
                uint32_t bd = base + 2 * ABYTES + swz((brow + j * 16) * 128 + kk * 32 + bcolb);
                ldm4(bd, Bh[j]);
                ldm4(bd + BBYTES, Bl[j]);
            }
#pragma unroll
            for (int mi = 0; mi < 4; mi++)
#pragma unroll
                for (int j = 0; j < 4; j++) {
                    mma_bf16(acc[mi][2 * j],     Ah[mi], Bh[j]);
                    mma_bf16(acc[mi][2 * j],     Ah[mi], Bl[j]);
                    mma_bf16(acc[mi][2 * j],     Al[mi], Bh[j]);
                    mma_bf16(acc[mi][2 * j + 1], Ah[mi], Bh[j] + 2);
                    mma_bf16(acc[mi][2 * j + 1], Ah[mi], Bl[j] + 2);
                    mma_bf16(acc[mi][2 * j + 1], Al[mi], Bh[j] + 2);
                }
        }
        __syncthreads();
    }

    // epilogue: C frag (c0,c1)=row l>>2, cols 2(l&3)+{0,1}; (c2,c3)=row+8
    const int grow = mt * 128 + wm * 64 + (lane >> 2);
    const int gcol = nt * 256 + wn * 64 + 2 * (lane & 3);
#pragma unroll
    for (int mi = 0; mi < 4; mi++) {
#pragma unroll
        for (int ni = 0; ni < 8; ni++) {
            float* p = g_G + (size_t)(grow + mi * 16) * GTOT + gcol + ni * 8;
            *(float2*)p = make_float2(acc[mi][ni][0], acc[mi][ni][1]);
            *(float2*)(p + (size_t)8 * GTOT) = make_float2(acc[mi][ni][2], acc[mi][ni][3]);
        }
    }
}

// -------- elementwise: gates, h update, y, next-step A --------
__global__ void elem_step_kernel(const int* __restrict__ item_idxs,
                                 const float* __restrict__ item_table,
                                 const float* __restrict__ b_ih,
                                 const float* __restrict__ b_hh,
                                 const float* __restrict__ W_out,
                                 const float* __restrict__ b_out,
                                 float* __restrict__ out, int s) {
    __shared__ float red[256];
    __shared__ float msh;
    const int n = blockIdx.x;
    const int d = threadIdx.x;
    const float* Gr = g_G + (size_t)n * GTOT;

    float r = sigmoidf_(Gr[d] + b_ih[d] + b_hh[d]);
    float z = sigmoidf_(Gr[256 + d] + b_ih[256 + d] + b_hh[256 + d]);
    float nv = tanhf(Gr[512 + d] + b_ih[512 + d] + r * (Gr[768 + d] + b_hh[512 + d]));
    float ho = g_h[n * DD + d];
    float hv = fmaf(z, ho - nv, nv);
    g_h[n * DD + d] = hv;

    red[d] = hv * W_out[d];
    __syncthreads();
#pragma unroll
    for (int off = 128; off > 0; off >>= 1) {
        if (d < off) red[d] += red[d + off];
        __syncthreads();
    }
    if (d == 0) {
        float y = red[0] + b_out[0];
        out[n * SLATE_ + s] = y;      // pre-sigmoid logit (reference returns y)
        msh = sigmoidf_(y);
    }
    __syncthreads();

    if (s + 1 < SLATE_) {
        float m = msh;
        float e = item_table[(size_t)item_idxs[n * SLATE_ + s + 1] * DD + d];
        __nv_bfloat16 hi, lo;
        split2(e, hi, lo);
        int a0 = a_addr(n, d);       g_A_hi[a0] = hi; g_A_lo[a0] = lo;
        split2(m * e, hi, lo);
        int a1 = a_addr(n, 256 + d); g_A_hi[a1] = hi; g_A_lo[a1] = lo;
        split2(hv, hi, lo);
        int a2 = a_addr(n, 512 + d); g_A_hi[a2] = hi; g_A_lo[a2] = lo;
    }
}

extern "C" void kernel_launch(void* const* d_in, const int* in_sizes, int n_in,
                              void* d_out, int out_size) {
    const int*   item_idxs  = (const int*)d_in[0];
    const int*   user_idxs  = (const int*)d_in[1];
    /* d_in[2] = responses (unused) */
    const float* item_table = (const float*)d_in[3];
    const float* user_table = (const float*)d_in[4];
    const float* W_ih       = (const float*)d_in[5];
    const float* W_hh       = (const float*)d_in[6];
    const float* b_ih       = (const float*)d_in[7];
    const float* b_hh       = (const float*)d_in[8];
    const float* W_out      = (const float*)d_in[9];
    const float* b_out      = (const float*)d_in[10];
    float* out = (float*)d_out;

    cudaFuncSetAttribute(gemm_step_kernel,
                         cudaFuncAttributeMaxDynamicSharedMemorySize, SMTOT);

    wsplit_kernel<<<(GTOT * KTOT + 255) / 256, 256>>>(W_ih, W_hh);
    prep0_kernel<<<NSEQT, 256>>>(item_idxs, user_idxs, item_table, user_table);
    for (int s = 0; s < SLATE_; s++) {
        gemm_step_kernel<<<NMT * NNT, 256, SMTOT>>>();
        elem_step_kernel<<<NSEQT, 256>>>(item_idxs, item_table, b_ih, b_hh,
                                         W_out, b_out, out, s);
    }
}

// round 11
// speedup vs baseline: 5.5880x; 1.6719x over previous
#include <cuda_runtime.h>
#include <cuda_fp16.h>
#include <cstdint>

// NeuralClickModel, round 9 (R8 design + compile fix).
// gi = e@W1^T + m*(e@W2^T) + b_ih ; gh = h@Whh^T + b_hh.
// P,Q = e@[W1|W2]^T precomputed for ALL 20 steps in ONE fp16 GEMM
// (M=81920, N=1536, K=256). Per step only h@Whh^T (M=4096, N=768, K=256)
// is on the serial path. Single fp16 MMA (no hi/lo split): rel err ~2e-4.
//
// Layouts: A/B operands pre-swizzled (SW128) blocked fp16 in gmem so GEMM
// staging is pure linear 16B cp.async. G_pre stored fp16, Gh fp32.

#define SLATE_ 20
#define NSEQ  4096
#define DD    256
#define KC    64
#define NKCH  4        // K=256 -> 4 chunks
#define MROWS_PRE 81920
#define NPRE  1536
#define NH    768

#define ABLK  (128 * KC)        // 8192 elems per A block
#define BBLK  (256 * KC)        // 16384 elems per B block
#define ABYT  (ABLK * 2)        // 16 KB
#define BBYT  (BBLK * 2)        // 32 KB
#define BUFB  (ABYT + BBYT)     // 48 KB per pipeline buffer
#define SMTOT (2 * BUFB)        // 96 KB

// -------- device scratch (static; no allocation) --------
__device__ __align__(16) __half g_Ae[MROWS_PRE * DD];        // 42 MB
__device__ __align__(16) __half g_Bpre[NPRE * DD];           // 768 KB
__device__ __align__(16) __half g_Bh[NH * DD];               // 384 KB
__device__ __align__(16) __half g_Ah[NSEQ * DD];             // 2 MB
__device__ __align__(16) __half g_Gpre[(size_t)MROWS_PRE * NPRE]; // 252 MB
__device__ __align__(16) float  g_Gh[NSEQ * NH];             // 12.6 MB
__device__ float g_h[NSEQ * DD];
__device__ float g_m[NSEQ];

// -------- helpers --------
__device__ __forceinline__ uint32_t h2_as_u32(__half2 h) {
    union { __half2 h2; uint32_t u; } cvt;
    cvt.h2 = h;
    return cvt.u;
}
__device__ __forceinline__ uint32_t smem_u32(const void* p) {
    uint32_t a;
    asm("{ .reg .u64 t; cvta.to.shared.u64 t, %1; cvt.u32.u64 %0, t; }" : "=r"(a) : "l"(p));
    return a;
}
__device__ __forceinline__ int swz(int byt) { return byt ^ ((byt >> 3) & 0x70); }
__device__ __forceinline__ void cp16(uint32_t s, const void* g) {
    asm volatile("cp.async.cg.shared.global [%0], [%1], 16;" :: "r"(s), "l"(g) : "memory");
}
__device__ __forceinline__ void cp_commit() {
    asm volatile("cp.async.commit_group;" ::: "memory");
}
template <int N> __device__ __forceinline__ void cp_wait() {
    asm volatile("cp.async.wait_group %0;" :: "n"(N) : "memory");
}
__device__ __forceinline__ void ldm4(uint32_t addr, uint32_t* r) {
    asm volatile("ldmatrix.sync.aligned.m8n8.x4.shared.b16 {%0,%1,%2,%3}, [%4];"
                 : "=r"(r[0]), "=r"(r[1]), "=r"(r[2]), "=r"(r[3]) : "r"(addr));
}
__device__ __forceinline__ void mma_fp16(float* d, const uint32_t* a, const uint32_t* b) {
    asm volatile(
        "mma.sync.aligned.m16n8k16.row.col.f32.f16.f16.f32 "
        "{%0,%1,%2,%3}, {%4,%5,%6,%7}, {%8,%9}, {%0,%1,%2,%3};"
        : "+f"(d[0]), "+f"(d[1]), "+f"(d[2]), "+f"(d[3])
        : "r"(a[0]), "r"(a[1]), "r"(a[2]), "r"(a[3]), "r"(b[0]), "r"(b[1]));
}
// blocked + swizzled gmem element index
__device__ __forceinline__ int a_idx(int r, int k) {
    int blk = (r >> 7) * NKCH + (k >> 6);
    return blk * ABLK + (swz((r & 127) * 128 + (k & 63) * 2) >> 1);
}
__device__ __forceinline__ int b_idx(int n, int k) {
    int blk = (n >> 8) * NKCH + (k >> 6);
    return blk * BBLK + (swz((n & 255) * 128 + (k & 63) * 2) >> 1);
}
__device__ __forceinline__ float sigmoidf_(float x) { return 1.0f / (1.0f + __expf(-x)); }

// -------- weight prep --------
__global__ void wsplit_pre_kernel(const float* __restrict__ W_ih) {
    int idx = blockIdx.x * blockDim.x + threadIdx.x;   // < 1536*256
    int n = idx >> 8, k = idx & 255;
    float w = (n < NH) ? W_ih[n * 512 + k] : W_ih[(n - NH) * 512 + 256 + k];
    g_Bpre[b_idx(n, k)] = __float2half_rn(w);
}
__global__ void wsplit_h_kernel(const float* __restrict__ W_hh) {
    int idx = blockIdx.x * blockDim.x + threadIdx.x;   // < 768*256
    int n = idx >> 8, k = idx & 255;
    g_Bh[b_idx(n, k)] = __float2half_rn(W_hh[n * 256 + k]);
}

// -------- embedding gather for all steps: rows r = s*4096 + n --------
__global__ void prep_e_kernel(const int* __restrict__ item_idxs,
                              const float* __restrict__ item_table) {
    int r = blockIdx.x * 8 + (threadIdx.x >> 5);
    int lane = threadIdx.x & 31;
    int n = r & (NSEQ - 1);
    int s = r >> 12;
    int iidx = item_idxs[n * SLATE_ + s];
    const float* src = item_table + (size_t)iidx * DD + lane * 8;
    float4 v0 = *(const float4*)src;
    float4 v1 = *(const float4*)(src + 4);
    uint4 h4;
    h4.x = h2_as_u32(__floats2half2_rn(v0.x, v0.y));
    h4.y = h2_as_u32(__floats2half2_rn(v0.z, v0.w));
    h4.z = h2_as_u32(__floats2half2_rn(v1.x, v1.y));
    h4.w = h2_as_u32(__floats2half2_rn(v1.z, v1.w));
    *(uint4*)(g_Ae + a_idx(r, lane * 8)) = h4;
}

// -------- h0 / m0 prep --------
__global__ void prep_h_kernel(const int* __restrict__ user_idxs,
                              const float* __restrict__ user_table) {
    int n = blockIdx.x;
    int d = threadIdx.x;
    float h0 = user_table[(size_t)user_idxs[n] * DD + d];
    g_h[n * DD + d] = h0;
    g_Ah[a_idx(n, d)] = __float2half_rn(h0);
    if (d == 0) g_m[n] = 1.0f;
}

// -------- shared GEMM body: C[M x N] = A[M x 256] @ B^T, fp16 in, OT out --------
template <typename OT>
__device__ __forceinline__ void gemm_body(const __half* __restrict__ gA,
                                          const __half* __restrict__ gB,
                                          OT* __restrict__ gC, int cpitch) {
    extern __shared__ char smem[];
    const uint32_t sb = smem_u32(smem);
    const int tid = threadIdx.x;
    const int lane = tid & 31;
    const int warp = tid >> 5;
    const int wm = warp & 1;
    const int wn = warp >> 1;
    const int mt = blockIdx.x;
    const int nt = blockIdx.y;

    const char* pA = (const char*)(gA + (size_t)mt * NKCH * ABLK);
    const char* pB = (const char*)(gB + (size_t)nt * NKCH * BBLK);

    float acc[4][8][4];
#pragma unroll
    for (int mi = 0; mi < 4; mi++)
#pragma unroll
        for (int ni = 0; ni < 8; ni++)
#pragma unroll
            for (int q = 0; q < 4; q++) acc[mi][ni][q] = 0.0f;

    const int arow  = wm * 64 + (lane & 15);
    const int acolb = (lane >> 4) * 16;
    const int brow  = wn * 64 + ((lane >> 4) << 3) + (lane & 7);
    const int bcolb = ((lane >> 3) & 1) * 16;

    // stage chunk 0
#pragma unroll
    for (int i = 0; i < 4; i++) {
        int o = (tid + i * 256) * 16;
        cp16(sb + o, pA + o);
    }
#pragma unroll
    for (int i = 0; i < 8; i++) {
        int o = (tid + i * 256) * 16;
        cp16(sb + ABYT + o, pB + o);
    }
    cp_commit();

#pragma unroll 1
    for (int c = 0; c < NKCH; c++) {
        const int buf = c & 1;
        if (c + 1 < NKCH) {
            const uint32_t d2 = sb + (buf ^ 1) * BUFB;
#pragma unroll
            for (int i = 0; i < 4; i++) {
                int o = (tid + i * 256) * 16;
                cp16(d2 + o, pA + (c + 1) * ABYT + o);
            }
#pragma unroll
            for (int i = 0; i < 8; i++) {
                int o = (tid + i * 256) * 16;
                cp16(d2 + ABYT + o, pB + (c + 1) * BBYT + o);
            }
            cp_commit();
            cp_wait<1>();
        } else {
            cp_wait<0>();
        }
        __syncthreads();

        const uint32_t base = sb + buf * BUFB;
#pragma unroll
        for (int kk = 0; kk < 4; kk++) {
            uint32_t Af[4][4];
#pragma unroll
            for (int mi = 0; mi < 4; mi++)
                ldm4(base + swz((arow + mi * 16) * 128 + kk * 32 + acolb), Af[mi]);
            uint32_t Bf[4][4];
#pragma unroll
            for (int j = 0; j < 4; j++)
                ldm4(base + ABYT + swz((brow + j * 16) * 128 + kk * 32 + bcolb), Bf[j]);
#pragma unroll
            for (int mi = 0; mi < 4; mi++)
#pragma unroll
                for (int j = 0; j < 4; j++) {
                    mma_fp16(acc[mi][2 * j],     Af[mi], Bf[j]);
                    mma_fp16(acc[mi][2 * j + 1], Af[mi], Bf[j] + 2);
                }
        }
        __syncthreads();
    }

    const int grow = mt * 128 + wm * 64 + (lane >> 2);
    const int gcol = nt * 256 + wn * 64 + 2 * (lane & 3);
#pragma unroll
    for (int mi = 0; mi < 4; mi++) {
#pragma unroll
        for (int ni = 0; ni < 8; ni++) {
            size_t p0 = (size_t)(grow + mi * 16) * cpitch + gcol + ni * 8;
            if constexpr (sizeof(OT) == 2) {
                *(__half2*)((__half*)gC + p0) =
                    __floats2half2_rn(acc[mi][ni][0], acc[mi][ni][1]);
                *(__half2*)((__half*)gC + p0 + (size_t)8 * cpitch) =
                    __floats2half2_rn(acc[mi][ni][2], acc[mi][ni][3]);
            } else {
                *(float2*)((float*)gC + p0) =
                    make_float2(acc[mi][ni][0], acc[mi][ni][1]);
                *(float2*)((float*)gC + p0 + (size_t)8 * cpitch) =
                    make_float2(acc[mi][ni][2], acc[mi][ni][3]);
            }
        }
    }
}

__global__ void __launch_bounds__(256, 1) gemm_pre_kernel() {
    gemm_body<__half>(g_Ae, g_Bpre, g_Gpre, NPRE);
}
__global__ void __launch_bounds__(256, 1) gemm_h_kernel() {
    gemm_body<float>(g_Ah, g_Bh, g_Gh, NH);
}

// -------- elementwise: warp per sequence, no block barriers --------
__global__ void elem_step_kernel(const float* __restrict__ b_ih,
                                 const float* __restrict__ b_hh,
                                 const float* __restrict__ W_out,
                                 const float* __restrict__ b_out,
                                 float* __restrict__ out, int s) {
    const int n = blockIdx.x * 8 + (threadIdx.x >> 5);
    const int lane = threadIdx.x & 31;
    const __half* Pr = g_Gpre + (size_t)(s * NSEQ + n) * NPRE;
    const float* Gh = g_Gh + (size_t)n * NH;
    const float m = g_m[n];
    float yp = 0.0f;

#pragma unroll
    for (int i = 0; i < 8; i++) {
        int d = lane + i * 32;
        float P_r = __half2float(Pr[d]);
        float P_z = __half2float(Pr[256 + d]);
        float P_n = __half2float(Pr[512 + d]);
        float Q_r = __half2float(Pr[768 + d]);
        float Q_z = __half2float(Pr[1024 + d]);
        float Q_n = __half2float(Pr[1280 + d]);
        float r = sigmoidf_(P_r + m * Q_r + b_ih[d] + Gh[d] + b_hh[d]);
        float z = sigmoidf_(P_z + m * Q_z + b_ih[256 + d] + Gh[256 + d] + b_hh[256 + d]);
        float nv = tanhf(P_n + m * Q_n + b_ih[512 + d] +
                         r * (Gh[512 + d] + b_hh[512 + d]));
        float ho = g_h[n * DD + d];
        float hv = fmaf(z, ho - nv, nv);
        g_h[n * DD + d] = hv;
        g_Ah[a_idx(n, d)] = __float2half_rn(hv);
        yp = fmaf(hv, W_out[d], yp);
    }
#pragma unroll
    for (int off = 16; off > 0; off >>= 1)
        yp += __shfl_xor_sync(0xffffffffu, yp, off);
    if (lane == 0) {
        float y = yp + b_out[0];
        out[n * SLATE_ + s] = y;
        g_m[n] = sigmoidf_(y);
    }
}

extern "C" void kernel_launch(void* const* d_in, const int* in_sizes, int n_in,
                              void* d_out, int out_size) {
    const int*   item_idxs  = (const int*)d_in[0];
    const int*   user_idxs  = (const int*)d_in[1];
    /* d_in[2] = responses (unused) */
    const float* item_table = (const float*)d_in[3];
    const float* user_table = (const float*)d_in[4];
    const float* W_ih       = (const float*)d_in[5];
    const float* W_hh       = (const float*)d_in[6];
    const float* b_ih       = (const float*)d_in[7];
    const float* b_hh       = (const float*)d_in[8];
    const float* W_out      = (const float*)d_in[9];
    const float* b_out      = (const float*)d_in[10];
    float* out = (float*)d_out;

    cudaFuncSetAttribute(gemm_pre_kernel,
                         cudaFuncAttributeMaxDynamicSharedMemorySize, SMTOT);
    cudaFuncSetAttribute(gemm_h_kernel,
                         cudaFuncAttributeMaxDynamicSharedMemorySize, SMTOT);

    wsplit_pre_kernel<<<NPRE * 256 / 256, 256>>>(W_ih);
    wsplit_h_kernel<<<NH * 256 / 256, 256>>>(W_hh);
    prep_e_kernel<<<MROWS_PRE / 8, 256>>>(item_idxs, item_table);
    prep_h_kernel<<<NSEQ, 256>>>(user_idxs, user_table);

    gemm_pre_kernel<<<dim3(MROWS_PRE / 128, NPRE / 256), 256, SMTOT>>>();

    for (int s = 0; s < SLATE_; s++) {
        gemm_h_kernel<<<dim3(NSEQ / 128, NH / 256), 256, SMTOT>>>();
        elem_step_kernel<<<NSEQ / 8, 256>>>(b_ih, b_hh, W_out, b_out, out, s);
    }
}